// round 1
// baseline (speedup 1.0000x reference)
#include <cuda_runtime.h>
#include <math.h>

#define NSP 9216        // 16*24*24
#define DD 16
#define HH 24
#define WW 24

// ---------------- scratch (device globals; no allocation allowed) ----------
__device__ float d_theta[NSP * 8];    // [n][c]
__device__ float d_phi[NSP * 8];      // [n][c]
__device__ float d_g[NSP * 32];       // [n][c]
__device__ float d_m[NSP];            // per-query max logit
__device__ float d_og[32 * NSP];      // attn output, [c][n]
__device__ float d_y[64 * NSP];       // o-conv output, [c][n]
__device__ float d_mean[64];
__device__ float d_rstd[64];

// ---------------- kernel 1: fused theta/phi/g conv3d (SAME, 3x3x3) --------
// grid: 48 blocks (8 d-tiles x 6 h-tiles), block: 192 threads (2x4x24 tile)
__global__ __launch_bounds__(192) void conv_qkv(
    const float* __restrict__ x,
    const float* __restrict__ tw, const float* __restrict__ tb,
    const float* __restrict__ pw, const float* __restrict__ pb,
    const float* __restrict__ gw, const float* __restrict__ gb)
{
    __shared__ float ws[8 * 27 * 48];   // [ci][tap][co], 41.5 KB

    const int tid = threadIdx.x;
    const int bd = blockIdx.x / 6, bh = blockIdx.x % 6;
    const int tz = tid / 96, ty = (tid / 24) % 4, tx = tid % 24;
    const int d = bd * 2 + tz, h = bh * 4 + ty, w = tx;

    float acc[48];
#pragma unroll
    for (int i = 0; i < 48; i++) acc[i] = 0.f;

    for (int cc = 0; cc < 8; cc++) {          // ci chunks of 8
        // stage weights: co 0-7 theta, 8-15 phi, 16-47 g
        for (int i = tid; i < 8 * 27 * 48; i += 192) {
            int ci  = i / (27 * 48);
            int rem = i % (27 * 48);
            int tap = rem / 48;
            int co  = rem % 48;
            int cig = cc * 8 + ci;
            float v;
            if (co < 8)        v = tw[(co * 64 + cig) * 27 + tap];
            else if (co < 16)  v = pw[((co - 8) * 64 + cig) * 27 + tap];
            else               v = gw[((co - 16) * 64 + cig) * 27 + tap];
            ws[(ci * 27 + tap) * 48 + co] = v;
        }
        __syncthreads();

        for (int ci = 0; ci < 8; ci++) {
            const int cig = cc * 8 + ci;
            const float* xb = x + cig * NSP;
            for (int kd = 0; kd < 3; kd++) {
                const int zd = d + kd - 1;
                for (int kh = 0; kh < 3; kh++) {
                    const int zh = h + kh - 1;
#pragma unroll
                    for (int kw = 0; kw < 3; kw++) {
                        const int zw = w + kw - 1;
                        float xv = 0.f;
                        if (zd >= 0 && zd < DD && zh >= 0 && zh < HH &&
                            zw >= 0 && zw < WW)
                            xv = __ldg(xb + zd * (HH * WW) + zh * WW + zw);
                        const float* wr =
                            &ws[(ci * 27 + (kd * 3 + kh) * 3 + kw) * 48];
#pragma unroll
                        for (int co = 0; co < 48; co++)
                            acc[co] += xv * wr[co];
                    }
                }
            }
        }
        __syncthreads();
    }

    const int n = d * (HH * WW) + h * WW + w;
#pragma unroll
    for (int c = 0; c < 8; c++)  d_theta[n * 8 + c]  = acc[c]      + tb[c];
#pragma unroll
    for (int c = 0; c < 8; c++)  d_phi[n * 8 + c]    = acc[8 + c]  + pb[c];
#pragma unroll
    for (int c = 0; c < 32; c++) d_g[n * 32 + c]     = acc[16 + c] + gb[c];
}

// ---------------- kernel 2: pass 1, per-query max logit --------------------
// grid: 36, block: 256 (one query per thread)
__global__ __launch_bounds__(256) void attn_max()
{
    __shared__ float ps[256 * 8];      // phi tile
    const int q = blockIdx.x * 256 + threadIdx.x;

    float th[8];
#pragma unroll
    for (int c = 0; c < 8; c++) th[c] = d_theta[q * 8 + c];

    float m = -1e30f;
    for (int kt = 0; kt < NSP / 256; kt++) {
        __syncthreads();
        {
            float4 a = ((const float4*)d_phi)[(kt * 256 + threadIdx.x) * 2 + 0];
            float4 b = ((const float4*)d_phi)[(kt * 256 + threadIdx.x) * 2 + 1];
            ((float4*)ps)[threadIdx.x * 2 + 0] = a;
            ((float4*)ps)[threadIdx.x * 2 + 1] = b;
        }
        __syncthreads();
        for (int k = 0; k < 256; k++) {
            float s = 0.f;
#pragma unroll
            for (int c = 0; c < 8; c++) s += th[c] * ps[k * 8 + c];
            m = fmaxf(m, s);
        }
    }
    d_m[q] = m;
}

// ---------------- kernel 3: pass 2, softmax + attn @ g ---------------------
// grid: 36, block: 256 (one query per thread)
__global__ __launch_bounds__(256) void attn_pv()
{
    __shared__ float ps[64 * 8];       // phi tile   (2 KB)
    __shared__ float gs[64 * 32];      // g tile     (8 KB)
    const int q = blockIdx.x * 256 + threadIdx.x;

    float th[8];
#pragma unroll
    for (int c = 0; c < 8; c++) th[c] = d_theta[q * 8 + c];
    const float m = d_m[q];

    float l = 0.f;
    float acc[32];
#pragma unroll
    for (int c = 0; c < 32; c++) acc[c] = 0.f;

    for (int kt = 0; kt < NSP / 64; kt++) {
        __syncthreads();
        for (int i = threadIdx.x; i < 64 * 8 / 4; i += 256)
            ((float4*)ps)[i] = ((const float4*)d_phi)[kt * 128 + i];
        for (int i = threadIdx.x; i < 64 * 32 / 4; i += 256)
            ((float4*)gs)[i] = ((const float4*)d_g)[kt * 512 + i];
        __syncthreads();

        for (int k = 0; k < 64; k++) {
            float s = 0.f;
#pragma unroll
            for (int c = 0; c < 8; c++) s += th[c] * ps[k * 8 + c];
            const float p = __expf(s - m);
            l += p;
#pragma unroll
            for (int c = 0; c < 32; c++) acc[c] += p * gs[k * 32 + c];
        }
    }

    const float inv = 1.f / l;
#pragma unroll
    for (int c = 0; c < 32; c++)
        d_og[c * NSP + q] = acc[c] * inv;
}

// ---------------- kernel 4: o-conv (64 out, 32 in, 3x3x3 SAME) -------------
// grid: 48, block: 192 (2x4x24 tile)
__global__ __launch_bounds__(192) void conv_o(
    const float* __restrict__ ow, const float* __restrict__ ob)
{
    __shared__ float ws[4 * 27 * 64];   // [ci][tap][co], 27.6 KB

    const int tid = threadIdx.x;
    const int bd = blockIdx.x / 6, bh = blockIdx.x % 6;
    const int tz = tid / 96, ty = (tid / 24) % 4, tx = tid % 24;
    const int d = bd * 2 + tz, h = bh * 4 + ty, w = tx;

    float acc[64];
#pragma unroll
    for (int i = 0; i < 64; i++) acc[i] = 0.f;

    for (int cc = 0; cc < 8; cc++) {      // ci chunks of 4
        for (int i = tid; i < 4 * 27 * 64; i += 192) {
            int ci  = i / (27 * 64);
            int rem = i % (27 * 64);
            int tap = rem / 64;
            int co  = rem % 64;
            int cig = cc * 4 + ci;
            ws[(ci * 27 + tap) * 64 + co] = ow[(co * 32 + cig) * 27 + tap];
        }
        __syncthreads();

        for (int ci = 0; ci < 4; ci++) {
            const float* xb = d_og + (cc * 4 + ci) * NSP;
            for (int kd = 0; kd < 3; kd++) {
                const int zd = d + kd - 1;
                for (int kh = 0; kh < 3; kh++) {
                    const int zh = h + kh - 1;
#pragma unroll
                    for (int kw = 0; kw < 3; kw++) {
                        const int zw = w + kw - 1;
                        float xv = 0.f;
                        if (zd >= 0 && zd < DD && zh >= 0 && zh < HH &&
                            zw >= 0 && zw < WW)
                            xv = __ldg(xb + zd * (HH * WW) + zh * WW + zw);
                        const float* wr =
                            &ws[(ci * 27 + (kd * 3 + kh) * 3 + kw) * 64];
#pragma unroll
                        for (int co = 0; co < 64; co++)
                            acc[co] += xv * wr[co];
                    }
                }
            }
        }
        __syncthreads();
    }

    const int n = d * (HH * WW) + h * WW + w;
#pragma unroll
    for (int co = 0; co < 64; co++)
        d_y[co * NSP + n] = acc[co] + ob[co];
}

// ---------------- kernel 5: BN stats (mean, rstd per channel) --------------
__global__ __launch_bounds__(256) void bn_stats()
{
    const int c = blockIdx.x;
    float s = 0.f, s2 = 0.f;
    for (int i = threadIdx.x; i < NSP; i += 256) {
        float v = d_y[c * NSP + i];
        s += v; s2 += v * v;
    }
#pragma unroll
    for (int o = 16; o > 0; o >>= 1) {
        s  += __shfl_down_sync(0xffffffffu, s,  o);
        s2 += __shfl_down_sync(0xffffffffu, s2, o);
    }
    __shared__ float shs[8], shs2[8];
    const int wid = threadIdx.x / 32, lid = threadIdx.x % 32;
    if (lid == 0) { shs[wid] = s; shs2[wid] = s2; }
    __syncthreads();
    if (threadIdx.x == 0) {
        float ts = 0.f, ts2 = 0.f;
#pragma unroll
        for (int i = 0; i < 8; i++) { ts += shs[i]; ts2 += shs2[i]; }
        const float mean = ts * (1.f / NSP);
        const float var  = ts2 * (1.f / NSP) - mean * mean;
        d_mean[c] = mean;
        d_rstd[c] = rsqrtf(var + 1e-5f);
    }
}

// ---------------- kernel 6: BN apply + residual + relu ---------------------
__global__ __launch_bounds__(256) void final_ew(
    const float* __restrict__ x,
    const float* __restrict__ gamma,
    const float* __restrict__ beta,
    float* __restrict__ out)
{
    const int idx = blockIdx.x * 256 + threadIdx.x;
    if (idx >= 64 * NSP) return;
    const int c = idx / NSP;
    const float yn = (d_y[idx] - d_mean[c]) * d_rstd[c] * gamma[c] + beta[c];
    const float v  = x[idx] + yn;
    out[idx] = v > 0.f ? v : 0.f;
}

// ---------------- launch ---------------------------------------------------
extern "C" void kernel_launch(void* const* d_in, const int* in_sizes, int n_in,
                              void* d_out, int out_size)
{
    (void)in_sizes; (void)n_in; (void)out_size;
    const float* x  = (const float*)d_in[0];
    const float* tw = (const float*)d_in[1];
    const float* tb = (const float*)d_in[2];
    const float* pw = (const float*)d_in[3];
    const float* pb = (const float*)d_in[4];
    const float* gw = (const float*)d_in[5];
    const float* gb = (const float*)d_in[6];
    const float* ow = (const float*)d_in[7];
    const float* ob = (const float*)d_in[8];
    const float* gamma = (const float*)d_in[9];
    const float* beta  = (const float*)d_in[10];
    float* out = (float*)d_out;

    conv_qkv<<<48, 192>>>(x, tw, tb, pw, pb, gw, gb);
    attn_max<<<NSP / 256, 256>>>();
    attn_pv<<<NSP / 256, 256>>>();
    conv_o<<<48, 192>>>(ow, ob);
    bn_stats<<<64, 256>>>();
    final_ew<<<(64 * NSP + 255) / 256, 256>>>(x, gamma, beta, out);
}

// round 2
// speedup vs baseline: 3.9632x; 3.9632x over previous
#include <cuda_runtime.h>
#include <math.h>

#define NSP 9216        // 16*24*24
#define DD 16
#define HH 24
#define WW 24
#define KS 16           // key splits for attention
#define KPS (NSP / KS)  // 576 keys per split

// ---------------- scratch (device globals; no allocation allowed) ----------
__device__ float d_theta[NSP * 8];        // [n][c]
__device__ float d_phi[NSP * 8];          // [n][c]
__device__ float d_g[NSP * 32];           // [n][c]
__device__ float d_pm[KS * NSP];          // partial max per split
__device__ float d_pl[KS * NSP];          // partial sum per split
__device__ float d_pacc[KS * NSP * 32];   // partial acc per split
__device__ float d_og[32 * NSP];          // attn output, [c][n]
__device__ float d_y[64 * NSP];           // o-conv output, [c][n]
__device__ float d_mean[64];
__device__ float d_rstd[64];

// ---------------- kernel 1: fused theta/phi/g conv3d (SAME, 3x3x3) --------
// grid: (48, 3) — 48 spatial tiles (2x4x24), 3 co-groups of 16
__global__ __launch_bounds__(192) void conv_qkv(
    const float* __restrict__ x,
    const float* __restrict__ tw, const float* __restrict__ tb,
    const float* __restrict__ pw, const float* __restrict__ pb,
    const float* __restrict__ gw, const float* __restrict__ gb)
{
    __shared__ float ws[8 * 27 * 16];   // [ci][tap][co], 13.5 KB

    const int tid = threadIdx.x;
    const int gy = blockIdx.y;                 // co-group
    const int bd = blockIdx.x / 6, bh = blockIdx.x % 6;
    const int tz = tid / 96, ty = (tid / 24) % 4, tx = tid % 24;
    const int d = bd * 2 + tz, h = bh * 4 + ty, w = tx;

    float acc[16];
#pragma unroll
    for (int i = 0; i < 16; i++) acc[i] = 0.f;

    for (int cc = 0; cc < 8; cc++) {          // ci chunks of 8
        for (int i = tid; i < 8 * 27 * 16; i += 192) {
            int ci  = i / (27 * 16);
            int rem = i % (27 * 16);
            int tap = rem / 16;
            int co  = rem % 16;
            int cig = cc * 8 + ci;
            float v;
            if (gy == 0)
                v = (co < 8) ? tw[(co * 64 + cig) * 27 + tap]
                             : pw[((co - 8) * 64 + cig) * 27 + tap];
            else {
                int cog = (gy - 1) * 16 + co;
                v = gw[(cog * 64 + cig) * 27 + tap];
            }
            ws[(ci * 27 + tap) * 16 + co] = v;
        }
        __syncthreads();

        for (int ci = 0; ci < 8; ci++) {
            const int cig = cc * 8 + ci;
            const float* xb = x + cig * NSP;
            for (int kd = 0; kd < 3; kd++) {
                const int zd = d + kd - 1;
                for (int kh = 0; kh < 3; kh++) {
                    const int zh = h + kh - 1;
#pragma unroll
                    for (int kw = 0; kw < 3; kw++) {
                        const int zw = w + kw - 1;
                        float xv = 0.f;
                        if (zd >= 0 && zd < DD && zh >= 0 && zh < HH &&
                            zw >= 0 && zw < WW)
                            xv = __ldg(xb + zd * (HH * WW) + zh * WW + zw);
                        const float* wr =
                            &ws[(ci * 27 + (kd * 3 + kh) * 3 + kw) * 16];
#pragma unroll
                        for (int co = 0; co < 16; co++)
                            acc[co] += xv * wr[co];
                    }
                }
            }
        }
        __syncthreads();
    }

    const int n = d * (HH * WW) + h * WW + w;
    if (gy == 0) {
#pragma unroll
        for (int c = 0; c < 8; c++) d_theta[n * 8 + c] = acc[c]     + tb[c];
#pragma unroll
        for (int c = 0; c < 8; c++) d_phi[n * 8 + c]   = acc[8 + c] + pb[c];
    } else {
        const int cb = (gy - 1) * 16;
#pragma unroll
        for (int c = 0; c < 16; c++)
            d_g[n * 32 + cb + c] = acc[c] + gb[cb + c];
    }
}

// ---------------- kernel 2: online-softmax attention, key-split ------------
// grid: (72, KS), block: 128 (one query per thread, KPS keys per block)
__global__ __launch_bounds__(128) void attn_split()
{
    __shared__ float ps[64 * 8];       // phi tile   (2 KB)
    __shared__ float gs[64 * 32];      // g tile     (8 KB)
    const int q  = blockIdx.x * 128 + threadIdx.x;
    const int ks = blockIdx.y;
    const int k0 = ks * KPS;

    float th[8];
#pragma unroll
    for (int c = 0; c < 8; c++) th[c] = d_theta[q * 8 + c];

    float m = -1e30f, l = 0.f;
    float acc[32];
#pragma unroll
    for (int c = 0; c < 32; c++) acc[c] = 0.f;

    for (int kt = 0; kt < KPS / 64; kt++) {
        __syncthreads();
        for (int i = threadIdx.x; i < 64 * 8 / 4; i += 128)
            ((float4*)ps)[i] = ((const float4*)(d_phi + (k0 + kt * 64) * 8))[i];
        for (int i = threadIdx.x; i < 64 * 32 / 4; i += 128)
            ((float4*)gs)[i] = ((const float4*)(d_g + (k0 + kt * 64) * 32))[i];
        __syncthreads();

        for (int k = 0; k < 64; k++) {
            float s = 0.f;
#pragma unroll
            for (int c = 0; c < 8; c++) s += th[c] * ps[k * 8 + c];
            if (s > m) {
                const float sc = __expf(m - s);
                l *= sc;
#pragma unroll
                for (int c = 0; c < 32; c++) acc[c] *= sc;
                m = s;
            }
            const float p = __expf(s - m);
            l += p;
#pragma unroll
            for (int c = 0; c < 32; c++) acc[c] += p * gs[k * 32 + c];
        }
    }

    d_pm[ks * NSP + q] = m;
    d_pl[ks * NSP + q] = l;
    float4* pa = (float4*)&d_pacc[(ks * (long)NSP + q) * 32];
#pragma unroll
    for (int j = 0; j < 8; j++)
        pa[j] = make_float4(acc[4 * j], acc[4 * j + 1],
                            acc[4 * j + 2], acc[4 * j + 3]);
}

// ---------------- kernel 3: merge splits, write attn out transposed --------
// grid: 72, block: 128 (one query per thread)
__global__ __launch_bounds__(128) void attn_combine()
{
    const int q = blockIdx.x * 128 + threadIdx.x;

    float m = -1e30f;
#pragma unroll
    for (int i = 0; i < KS; i++) m = fmaxf(m, d_pm[i * NSP + q]);

    float l = 0.f;
    float acc[32];
#pragma unroll
    for (int c = 0; c < 32; c++) acc[c] = 0.f;

    for (int i = 0; i < KS; i++) {
        const float wgt = __expf(d_pm[i * NSP + q] - m);
        l += d_pl[i * NSP + q] * wgt;
        const float4* pa = (const float4*)&d_pacc[(i * (long)NSP + q) * 32];
#pragma unroll
        for (int j = 0; j < 8; j++) {
            float4 v = pa[j];
            acc[4 * j]     += wgt * v.x;
            acc[4 * j + 1] += wgt * v.y;
            acc[4 * j + 2] += wgt * v.z;
            acc[4 * j + 3] += wgt * v.w;
        }
    }

    const float inv = 1.f / l;
#pragma unroll
    for (int c = 0; c < 32; c++)
        d_og[c * NSP + q] = acc[c] * inv;
}

// ---------------- kernel 4: o-conv (64 out, 32 in, 3x3x3 SAME) -------------
// grid: (48, 4) — 48 spatial tiles, 4 co-groups of 16
__global__ __launch_bounds__(192) void conv_o(
    const float* __restrict__ ow, const float* __restrict__ ob)
{
    __shared__ float ws[8 * 27 * 16];   // [ci][tap][co], 13.5 KB

    const int tid = threadIdx.x;
    const int gy = blockIdx.y;
    const int bd = blockIdx.x / 6, bh = blockIdx.x % 6;
    const int tz = tid / 96, ty = (tid / 24) % 4, tx = tid % 24;
    const int d = bd * 2 + tz, h = bh * 4 + ty, w = tx;

    float acc[16];
#pragma unroll
    for (int i = 0; i < 16; i++) acc[i] = 0.f;

    for (int cc = 0; cc < 4; cc++) {      // ci chunks of 8 (32 total)
        for (int i = tid; i < 8 * 27 * 16; i += 192) {
            int ci  = i / (27 * 16);
            int rem = i % (27 * 16);
            int tap = rem / 16;
            int co  = rem % 16;
            int cig = cc * 8 + ci;
            int cog = gy * 16 + co;
            ws[(ci * 27 + tap) * 16 + co] = ow[(cog * 32 + cig) * 27 + tap];
        }
        __syncthreads();

        for (int ci = 0; ci < 8; ci++) {
            const float* xb = d_og + (cc * 8 + ci) * NSP;
            for (int kd = 0; kd < 3; kd++) {
                const int zd = d + kd - 1;
                for (int kh = 0; kh < 3; kh++) {
                    const int zh = h + kh - 1;
#pragma unroll
                    for (int kw = 0; kw < 3; kw++) {
                        const int zw = w + kw - 1;
                        float xv = 0.f;
                        if (zd >= 0 && zd < DD && zh >= 0 && zh < HH &&
                            zw >= 0 && zw < WW)
                            xv = __ldg(xb + zd * (HH * WW) + zh * WW + zw);
                        const float* wr =
                            &ws[(ci * 27 + (kd * 3 + kh) * 3 + kw) * 16];
#pragma unroll
                        for (int co = 0; co < 16; co++)
                            acc[co] += xv * wr[co];
                    }
                }
            }
        }
        __syncthreads();
    }

    const int n = d * (HH * WW) + h * WW + w;
#pragma unroll
    for (int co = 0; co < 16; co++)
        d_y[(gy * 16 + co) * NSP + n] = acc[co] + ob[gy * 16 + co];
}

// ---------------- kernel 5: BN stats (mean, rstd per channel) --------------
__global__ __launch_bounds__(256) void bn_stats()
{
    const int c = blockIdx.x;
    float s = 0.f, s2 = 0.f;
    for (int i = threadIdx.x; i < NSP; i += 256) {
        float v = d_y[c * NSP + i];
        s += v; s2 += v * v;
    }
#pragma unroll
    for (int o = 16; o > 0; o >>= 1) {
        s  += __shfl_down_sync(0xffffffffu, s,  o);
        s2 += __shfl_down_sync(0xffffffffu, s2, o);
    }
    __shared__ float shs[8], shs2[8];
    const int wid = threadIdx.x / 32, lid = threadIdx.x % 32;
    if (lid == 0) { shs[wid] = s; shs2[wid] = s2; }
    __syncthreads();
    if (threadIdx.x == 0) {
        float ts = 0.f, ts2 = 0.f;
#pragma unroll
        for (int i = 0; i < 8; i++) { ts += shs[i]; ts2 += shs2[i]; }
        const float mean = ts * (1.f / NSP);
        const float var  = ts2 * (1.f / NSP) - mean * mean;
        d_mean[c] = mean;
        d_rstd[c] = rsqrtf(var + 1e-5f);
    }
}

// ---------------- kernel 6: BN apply + residual + relu ---------------------
__global__ __launch_bounds__(256) void final_ew(
    const float* __restrict__ x,
    const float* __restrict__ gamma,
    const float* __restrict__ beta,
    float* __restrict__ out)
{
    const int idx = blockIdx.x * 256 + threadIdx.x;
    if (idx >= 64 * NSP) return;
    const int c = idx / NSP;
    const float yn = (d_y[idx] - d_mean[c]) * d_rstd[c] * gamma[c] + beta[c];
    const float v  = x[idx] + yn;
    out[idx] = v > 0.f ? v : 0.f;
}

// ---------------- launch ---------------------------------------------------
extern "C" void kernel_launch(void* const* d_in, const int* in_sizes, int n_in,
                              void* d_out, int out_size)
{
    (void)in_sizes; (void)n_in; (void)out_size;
    const float* x  = (const float*)d_in[0];
    const float* tw = (const float*)d_in[1];
    const float* tb = (const float*)d_in[2];
    const float* pw = (const float*)d_in[3];
    const float* pb = (const float*)d_in[4];
    const float* gw = (const float*)d_in[5];
    const float* gb = (const float*)d_in[6];
    const float* ow = (const float*)d_in[7];
    const float* ob = (const float*)d_in[8];
    const float* gamma = (const float*)d_in[9];
    const float* beta  = (const float*)d_in[10];
    float* out = (float*)d_out;

    conv_qkv<<<dim3(48, 3), 192>>>(x, tw, tb, pw, pb, gw, gb);
    attn_split<<<dim3(NSP / 128, KS), 128>>>();
    attn_combine<<<NSP / 128, 128>>>();
    conv_o<<<dim3(48, 4), 192>>>(ow, ob);
    bn_stats<<<64, 256>>>();
    final_ew<<<(64 * NSP + 255) / 256, 256>>>(x, gamma, beta, out);
}

// round 4
// speedup vs baseline: 4.7321x; 1.1940x over previous
#include <cuda_runtime.h>
#include <math.h>

#define NSP 9216        // 16*24*24
#define DD 16
#define HH 24
#define WW 24
#define KS 16           // key splits for attention
#define KPS (NSP / KS)  // 576 keys per split

typedef unsigned long long ull;

// ---------------- f32x2 packed helpers (sm_100+) ---------------------------
__device__ __forceinline__ ull pack2(float lo, float hi) {
    ull r;
    asm("mov.b64 %0, {%1, %2};" : "=l"(r) : "f"(lo), "f"(hi));
    return r;
}
__device__ __forceinline__ float2 unpack2(ull v) {
    float2 f;
    asm("mov.b64 {%0, %1}, %2;" : "=f"(f.x), "=f"(f.y) : "l"(v));
    return f;
}
__device__ __forceinline__ void fma2(ull& d, ull a, ull b) {
    asm("fma.rn.f32x2 %0, %1, %2, %3;" : "=l"(d) : "l"(a), "l"(b), "l"(d));
}
__device__ __forceinline__ ull mul2(ull a, ull b) {
    ull r;
    asm("mul.rn.f32x2 %0, %1, %2;" : "=l"(r) : "l"(a), "l"(b));
    return r;
}

// ---------------- scratch (device globals; no allocation allowed) ----------
__device__ __align__(16) float d_theta[NSP * 8];      // [n][c]
__device__ __align__(16) float d_phi[NSP * 8];        // [n][c]
__device__ __align__(16) float d_g[NSP * 32];         // [n][c]
__device__ __align__(16) float d_pm[KS * NSP];        // partial max
__device__ __align__(16) float d_pl[KS * NSP];        // partial sum
__device__ __align__(16) float d_pacc[KS * NSP * 32]; // partial acc
__device__ __align__(16) float d_og[32 * NSP];        // attn out, [c][n]
__device__ __align__(16) float d_y[64 * NSP];         // o-conv out, [c][n]
__device__ float d_mean[64];
__device__ float d_rstd[64];

// ---------------- kernel 1: fused theta/phi/g conv3d -----------------------
// grid: (96, 3) — 96 spatial tiles (1x4x24), 3 co-groups of 16
__global__ __launch_bounds__(96) void conv_qkv(
    const float* __restrict__ x,
    const float* __restrict__ tw, const float* __restrict__ tb,
    const float* __restrict__ pw, const float* __restrict__ pb,
    const float* __restrict__ gw, const float* __restrict__ gb)
{
    __shared__ __align__(16) float ws[8 * 27 * 16];   // [ci][tap][co]

    const int tid = threadIdx.x;
    const int gy = blockIdx.y;
    const int d = blockIdx.x / 6;
    const int h = (blockIdx.x % 6) * 4 + tid / 24;
    const int w = tid % 24;

    // hoist tap offsets + validity mask
    int off[27];
    unsigned msk = 0;
    {
        int t = 0;
        for (int kd = 0; kd < 3; kd++)
            for (int kh = 0; kh < 3; kh++)
                for (int kw = 0; kw < 3; kw++, t++) {
                    const int zd = d + kd - 1, zh = h + kh - 1, zw = w + kw - 1;
                    const bool v = (zd >= 0 && zd < DD && zh >= 0 && zh < HH &&
                                    zw >= 0 && zw < WW);
                    off[t] = v ? (zd * (HH * WW) + zh * WW + zw) : 0;
                    if (v) msk |= 1u << t;
                }
    }

    ull acc2[8];
#pragma unroll
    for (int j = 0; j < 8; j++) acc2[j] = 0ull;

    for (int cc = 0; cc < 8; cc++) {          // ci chunks of 8
        for (int i = tid; i < 8 * 27 * 16; i += 96) {
            int ci  = i / (27 * 16);
            int rem = i % (27 * 16);
            int tap = rem / 16;
            int co  = rem % 16;
            int cig = cc * 8 + ci;
            float v;
            if (gy == 0)
                v = (co < 8) ? tw[(co * 64 + cig) * 27 + tap]
                             : pw[((co - 8) * 64 + cig) * 27 + tap];
            else {
                int cog = (gy - 1) * 16 + co;
                v = gw[(cog * 64 + cig) * 27 + tap];
            }
            ws[(ci * 27 + tap) * 16 + co] = v;
        }
        __syncthreads();

#pragma unroll 2
        for (int ci = 0; ci < 8; ci++) {
            const float* xb = x + (cc * 8 + ci) * NSP;
            float xv[27];
#pragma unroll
            for (int t = 0; t < 27; t++)
                xv[t] = ((msk >> t) & 1) ? __ldg(xb + off[t]) : 0.f;
#pragma unroll
            for (int t = 0; t < 27; t++) {
                const ull x2 = pack2(xv[t], xv[t]);
                const ulonglong2* wr =
                    (const ulonglong2*)&ws[(ci * 27 + t) * 16];
#pragma unroll
                for (int j = 0; j < 4; j++) {
                    ulonglong2 wv = wr[j];
                    fma2(acc2[2 * j],     x2, wv.x);
                    fma2(acc2[2 * j + 1], x2, wv.y);
                }
            }
        }
        __syncthreads();
    }

    float acc[16];
#pragma unroll
    for (int j = 0; j < 8; j++) {
        float2 u = unpack2(acc2[j]);
        acc[2 * j] = u.x; acc[2 * j + 1] = u.y;
    }

    const int n = d * (HH * WW) + h * WW + w;
    if (gy == 0) {
#pragma unroll
        for (int c = 0; c < 8; c++) d_theta[n * 8 + c] = acc[c]     + tb[c];
#pragma unroll
        for (int c = 0; c < 8; c++) d_phi[n * 8 + c]   = acc[8 + c] + pb[c];
    } else {
        const int cb = (gy - 1) * 16;
#pragma unroll
        for (int c = 0; c < 16; c++)
            d_g[n * 32 + cb + c] = acc[c] + gb[cb + c];
    }
}

// ---------------- kernel 2: online-softmax attention, key-split ------------
// grid: (36, KS), block: 128; each thread owns 2 queries (t, t+128)
__global__ __launch_bounds__(128) void attn_split()
{
    __shared__ __align__(16) float ps[64 * 8];    // phi tile
    __shared__ __align__(16) float gs[64 * 32];   // g tile
    const int t  = threadIdx.x;
    const int q0 = blockIdx.x * 256 + t;
    const int q1 = q0 + 128;
    const int k0 = blockIdx.y * KPS;

    ull th0[4], th1[4];
    {
        const ulonglong2* p0 = (const ulonglong2*)&d_theta[q0 * 8];
        ulonglong2 a = p0[0], b = p0[1];
        th0[0] = a.x; th0[1] = a.y; th0[2] = b.x; th0[3] = b.y;
        const ulonglong2* p1 = (const ulonglong2*)&d_theta[q1 * 8];
        ulonglong2 c = p1[0], e = p1[1];
        th1[0] = c.x; th1[1] = c.y; th1[2] = e.x; th1[3] = e.y;
    }

    float m0 = -1e30f, l0 = 0.f, m1 = -1e30f, l1 = 0.f;
    ull a0[16], a1[16];
#pragma unroll
    for (int j = 0; j < 16; j++) { a0[j] = 0ull; a1[j] = 0ull; }

    for (int kt = 0; kt < KPS / 64; kt++) {
        __syncthreads();
        ((float4*)ps)[t] = ((const float4*)(d_phi + (k0 + kt * 64) * 8))[t];
        {
            const float4* src = (const float4*)(d_g + (k0 + kt * 64) * 32);
#pragma unroll
            for (int i = 0; i < 4; i++)
                ((float4*)gs)[t + i * 128] = src[t + i * 128];
        }
        __syncthreads();

        for (int k = 0; k < 64; k++) {
            const ulonglong2* pp = (const ulonglong2*)&ps[k * 8];
            const ulonglong2 pA = pp[0], pB = pp[1];

            ull s2 = mul2(th0[0], pA.x);
            fma2(s2, th0[1], pA.y); fma2(s2, th0[2], pB.x); fma2(s2, th0[3], pB.y);
            float2 sf0 = unpack2(s2);
            const float s_0 = sf0.x + sf0.y;

            ull u2 = mul2(th1[0], pA.x);
            fma2(u2, th1[1], pA.y); fma2(u2, th1[2], pB.x); fma2(u2, th1[3], pB.y);
            float2 sf1 = unpack2(u2);
            const float s_1 = sf1.x + sf1.y;

            if (s_0 > m0) {
                const float sc = __expf(m0 - s_0);
                const ull sc2 = pack2(sc, sc);
                l0 *= sc;
#pragma unroll
                for (int j = 0; j < 16; j++) a0[j] = mul2(a0[j], sc2);
                m0 = s_0;
            }
            if (s_1 > m1) {
                const float sc = __expf(m1 - s_1);
                const ull sc2 = pack2(sc, sc);
                l1 *= sc;
#pragma unroll
                for (int j = 0; j < 16; j++) a1[j] = mul2(a1[j], sc2);
                m1 = s_1;
            }
            const float p0v = __expf(s_0 - m0);
            const float p1v = __expf(s_1 - m1);
            l0 += p0v; l1 += p1v;
            const ull p02 = pack2(p0v, p0v);
            const ull p12 = pack2(p1v, p1v);

            const ulonglong2* gg = (const ulonglong2*)&gs[k * 32];
#pragma unroll
            for (int j = 0; j < 8; j++) {
                ulonglong2 gv = gg[j];
                fma2(a0[2 * j],     p02, gv.x);
                fma2(a0[2 * j + 1], p02, gv.y);
                fma2(a1[2 * j],     p12, gv.x);
                fma2(a1[2 * j + 1], p12, gv.y);
            }
        }
    }

    const int ks = blockIdx.y;
    d_pm[ks * NSP + q0] = m0; d_pl[ks * NSP + q0] = l0;
    d_pm[ks * NSP + q1] = m1; d_pl[ks * NSP + q1] = l1;
    {
        ulonglong2* pa = (ulonglong2*)&d_pacc[((size_t)ks * NSP + q0) * 32];
#pragma unroll
        for (int j = 0; j < 8; j++)
            pa[j] = make_ulonglong2(a0[2 * j], a0[2 * j + 1]);
        ulonglong2* pb = (ulonglong2*)&d_pacc[((size_t)ks * NSP + q1) * 32];
#pragma unroll
        for (int j = 0; j < 8; j++)
            pb[j] = make_ulonglong2(a1[2 * j], a1[2 * j + 1]);
    }
}

// ---------------- kernel 3: merge splits, write attn out transposed --------
__global__ __launch_bounds__(128) void attn_combine()
{
    const int q = blockIdx.x * 128 + threadIdx.x;

    float m = -1e30f;
#pragma unroll
    for (int i = 0; i < KS; i++) m = fmaxf(m, d_pm[i * NSP + q]);

    float l = 0.f;
    float acc[32];
#pragma unroll
    for (int c = 0; c < 32; c++) acc[c] = 0.f;

    for (int i = 0; i < KS; i++) {
        const float wgt = __expf(d_pm[i * NSP + q] - m);
        l += d_pl[i * NSP + q] * wgt;
        const float4* pa = (const float4*)&d_pacc[((size_t)i * NSP + q) * 32];
#pragma unroll
        for (int j = 0; j < 8; j++) {
            float4 v = pa[j];
            acc[4 * j]     += wgt * v.x;
            acc[4 * j + 1] += wgt * v.y;
            acc[4 * j + 2] += wgt * v.z;
            acc[4 * j + 3] += wgt * v.w;
        }
    }

    const float inv = 1.f / l;
#pragma unroll
    for (int c = 0; c < 32; c++)
        d_og[c * NSP + q] = acc[c] * inv;
}

// ---------------- kernel 4: o-conv (64 out, 32 in) -------------------------
// grid: (96, 4) — 96 spatial tiles (1x4x24), 4 co-groups of 16
__global__ __launch_bounds__(96) void conv_o(
    const float* __restrict__ ow, const float* __restrict__ ob)
{
    __shared__ __align__(16) float ws[8 * 27 * 16];

    const int tid = threadIdx.x;
    const int gy = blockIdx.y;
    const int d = blockIdx.x / 6;
    const int h = (blockIdx.x % 6) * 4 + tid / 24;
    const int w = tid % 24;

    int off[27];
    unsigned msk = 0;
    {
        int t = 0;
        for (int kd = 0; kd < 3; kd++)
            for (int kh = 0; kh < 3; kh++)
                for (int kw = 0; kw < 3; kw++, t++) {
                    const int zd = d + kd - 1, zh = h + kh - 1, zw = w + kw - 1;
                    const bool v = (zd >= 0 && zd < DD && zh >= 0 && zh < HH &&
                                    zw >= 0 && zw < WW);
                    off[t] = v ? (zd * (HH * WW) + zh * WW + zw) : 0;
                    if (v) msk |= 1u << t;
                }
    }

    ull acc2[8];
#pragma unroll
    for (int j = 0; j < 8; j++) acc2[j] = 0ull;

    for (int cc = 0; cc < 4; cc++) {      // ci chunks of 8 (32 total)
        for (int i = tid; i < 8 * 27 * 16; i += 96) {
            int ci  = i / (27 * 16);
            int rem = i % (27 * 16);
            int tap = rem / 16;
            int co  = rem % 16;
            ws[(ci * 27 + tap) * 16 + co] =
                ow[((gy * 16 + co) * 32 + cc * 8 + ci) * 27 + tap];
        }
        __syncthreads();

#pragma unroll 2
        for (int ci = 0; ci < 8; ci++) {
            const float* xb = d_og + (cc * 8 + ci) * NSP;
            float xv[27];
#pragma unroll
            for (int t = 0; t < 27; t++)
                xv[t] = ((msk >> t) & 1) ? __ldg(xb + off[t]) : 0.f;
#pragma unroll
            for (int t = 0; t < 27; t++) {
                const ull x2 = pack2(xv[t], xv[t]);
                const ulonglong2* wr =
                    (const ulonglong2*)&ws[(ci * 27 + t) * 16];
#pragma unroll
                for (int j = 0; j < 4; j++) {
                    ulonglong2 wv = wr[j];
                    fma2(acc2[2 * j],     x2, wv.x);
                    fma2(acc2[2 * j + 1], x2, wv.y);
                }
            }
        }
        __syncthreads();
    }

    const int n = d * (HH * WW) + h * WW + w;
#pragma unroll
    for (int j = 0; j < 8; j++) {
        float2 u = unpack2(acc2[j]);
        d_y[(gy * 16 + 2 * j)     * NSP + n] = u.x + ob[gy * 16 + 2 * j];
        d_y[(gy * 16 + 2 * j + 1) * NSP + n] = u.y + ob[gy * 16 + 2 * j + 1];
    }
}

// ---------------- kernel 5: BN stats ---------------------------------------
__global__ __launch_bounds__(256) void bn_stats()
{
    const int c = blockIdx.x;
    float s = 0.f, s2 = 0.f;
    for (int i = threadIdx.x; i < NSP; i += 256) {
        float v = d_y[c * NSP + i];
        s += v; s2 += v * v;
    }
#pragma unroll
    for (int o = 16; o > 0; o >>= 1) {
        s  += __shfl_down_sync(0xffffffffu, s,  o);
        s2 += __shfl_down_sync(0xffffffffu, s2, o);
    }
    __shared__ float shs[8], shs2[8];
    const int wid = threadIdx.x / 32, lid = threadIdx.x % 32;
    if (lid == 0) { shs[wid] = s; shs2[wid] = s2; }
    __syncthreads();
    if (threadIdx.x == 0) {
        float ts = 0.f, ts2 = 0.f;
#pragma unroll
        for (int i = 0; i < 8; i++) { ts += shs[i]; ts2 += shs2[i]; }
        const float mean = ts * (1.f / NSP);
        const float var  = ts2 * (1.f / NSP) - mean * mean;
        d_mean[c] = mean;
        d_rstd[c] = rsqrtf(var + 1e-5f);
    }
}

// ---------------- kernel 6: BN apply + residual + relu ---------------------
__global__ __launch_bounds__(256) void final_ew(
    const float* __restrict__ x,
    const float* __restrict__ gamma,
    const float* __restrict__ beta,
    float* __restrict__ out)
{
    const int idx = blockIdx.x * 256 + threadIdx.x;
    if (idx >= 64 * NSP) return;
    const int c = idx / NSP;
    const float yn = (d_y[idx] - d_mean[c]) * d_rstd[c] * gamma[c] + beta[c];
    const float v  = x[idx] + yn;
    out[idx] = v > 0.f ? v : 0.f;
}

// ---------------- launch ---------------------------------------------------
extern "C" void kernel_launch(void* const* d_in, const int* in_sizes, int n_in,
                              void* d_out, int out_size)
{
    (void)in_sizes; (void)n_in; (void)out_size;
    const float* x  = (const float*)d_in[0];
    const float* tw = (const float*)d_in[1];
    const float* tb = (const float*)d_in[2];
    const float* pw = (const float*)d_in[3];
    const float* pb = (const float*)d_in[4];
    const float* gw = (const float*)d_in[5];
    const float* gb = (const float*)d_in[6];
    const float* ow = (const float*)d_in[7];
    const float* ob = (const float*)d_in[8];
    const float* gamma = (const float*)d_in[9];
    const float* beta  = (const float*)d_in[10];
    float* out = (float*)d_out;

    conv_qkv<<<dim3(96, 3), 96>>>(x, tw, tb, pw, pb, gw, gb);
    attn_split<<<dim3(NSP / 256, KS), 128>>>();
    attn_combine<<<NSP / 128, 128>>>();
    conv_o<<<dim3(96, 4), 96>>>(ow, ob);
    bn_stats<<<64, 256>>>();
    final_ew<<<(64 * NSP + 255) / 256, 256>>>(x, gamma, beta, out);
}